// round 2
// baseline (speedup 1.0000x reference)
#include <cuda_runtime.h>
#include <cuda_bf16.h>
#include <cstdint>

// NT-Xent fused: N=4096, Z=128, T=0.5
#define TWO_N 8192
#define ZD 128
#define INV_T 2.0f
#define EXP_SCALE 2.8853900817779268f   // INV_T * log2(e)

#define BM 128
#define BN 128
#define STRIDE 136                       // bf16 elems per smem row (128 + 8 pad)
#define SMEM_SZ (2 * BM * STRIDE * 2)    // 69632 bytes

// Scratch (device globals — no allocation allowed)
__device__ __nv_bfloat16 g_nrep_bf16[TWO_N * ZD];
__device__ float         g_nrep_f32 [TWO_N * ZD];
__device__ float         g_rowsum  [TWO_N];
__device__ float         g_pos     [TWO_N];

// ---------------------------------------------------------------------------
// Kernel 1: row-normalize reps = concat(z1, z2); emit f32 + bf16; zero rowsum
// ---------------------------------------------------------------------------
__global__ void normalize_kernel(const float* __restrict__ z1,
                                 const float* __restrict__ z2) {
    int row = blockIdx.x;
    int t = threadIdx.x;
    const float* src = (row < TWO_N / 2) ? (z1 + (size_t)row * ZD)
                                         : (z2 + (size_t)(row - TWO_N / 2) * ZD);
    float v = src[t];
    float s = v * v;
    #pragma unroll
    for (int o = 16; o > 0; o >>= 1) s += __shfl_xor_sync(0xFFFFFFFFu, s, o);
    __shared__ float ws[4];
    int lane = t & 31, wid = t >> 5;
    if (lane == 0) ws[wid] = s;
    __syncthreads();
    float tot = ws[0] + ws[1] + ws[2] + ws[3];
    float scale = 1.0f / fmaxf(sqrtf(tot), 1e-8f);
    float nv = v * scale;
    g_nrep_f32 [row * ZD + t] = nv;
    g_nrep_bf16[row * ZD + t] = __float2bfloat16(nv);
    if (t == 0) g_rowsum[row] = 0.0f;
}

// ---------------------------------------------------------------------------
// Kernel 2: positives in fp32 — pos[i] = dot(nrep[i], nrep[(i+N) mod 2N])
// ---------------------------------------------------------------------------
__global__ void pos_kernel() {
    int wid = threadIdx.x >> 5, lane = threadIdx.x & 31;
    int row = blockIdx.x * 8 + wid;
    int peer = (row + TWO_N / 2) & (TWO_N - 1);
    const float* a = g_nrep_f32 + (size_t)row  * ZD;
    const float* b = g_nrep_f32 + (size_t)peer * ZD;
    float acc = 0.0f;
    #pragma unroll
    for (int k = lane; k < ZD; k += 32) acc = fmaf(a[k], b[k], acc);
    #pragma unroll
    for (int o = 16; o > 0; o >>= 1) acc += __shfl_xor_sync(0xFFFFFFFFu, acc, o);
    if (lane == 0) g_pos[row] = acc;
}

// ---------------------------------------------------------------------------
// Kernel 3: fused sim GEMM (mma.sync bf16) + exp + diag mask + row sums
// CTA = 128x128 sim tile, 256 threads = 8 warps (4 m x 2 n), warp tile 32x64.
// ---------------------------------------------------------------------------
__global__ void __launch_bounds__(256, 2) simgemm_kernel() {
    extern __shared__ __nv_bfloat16 smem[];
    __nv_bfloat16* sA = smem;
    __nv_bfloat16* sB = smem + BM * STRIDE;

    int tid = threadIdx.x;
    int wid = tid >> 5, lane = tid & 31;
    int rowBase = blockIdx.y * BM;
    int colBase = blockIdx.x * BN;

    // ---- Load A/B tiles [128 x 128] bf16 into padded smem (uint4 = 8 bf16)
    #pragma unroll
    for (int it = 0; it < 8; it++) {
        int idx = it * 256 + tid;          // 2048 16B-chunks per tile
        int r = idx >> 4, c = idx & 15;
        uint4 va = *(const uint4*)(g_nrep_bf16 + (size_t)(rowBase + r) * ZD + c * 8);
        *(uint4*)(sA + r * STRIDE + c * 8) = va;
        uint4 vb = *(const uint4*)(g_nrep_bf16 + (size_t)(colBase + r) * ZD + c * 8);
        *(uint4*)(sB + r * STRIDE + c * 8) = vb;
    }
    __syncthreads();

    int wm = wid & 3;        // warp row (4)
    int wn = wid >> 2;       // warp col (2)

    float acc[2][8][4];
    #pragma unroll
    for (int mt = 0; mt < 2; mt++)
        #pragma unroll
        for (int nt = 0; nt < 8; nt++)
            #pragma unroll
            for (int e = 0; e < 4; e++) acc[mt][nt][e] = 0.0f;

    // ldmatrix base addresses (per lane); k advances by 32B per k-step
    uint32_t aAddr[2];
    #pragma unroll
    for (int mt = 0; mt < 2; mt++) {
        int row = wm * 32 + mt * 16 + (lane & 15);
        int k = (lane >> 4) * 8;
        aAddr[mt] = (uint32_t)__cvta_generic_to_shared(sA + row * STRIDE + k);
    }
    uint32_t bAddr[4];
    #pragma unroll
    for (int ntp = 0; ntp < 4; ntp++) {
        int n = wn * 64 + ntp * 16 + ((lane >> 4) & 1) * 8 + (lane & 7);
        int k = ((lane >> 3) & 1) * 8;
        bAddr[ntp] = (uint32_t)__cvta_generic_to_shared(sB + n * STRIDE + k);
    }

    // ---- Mainloop: 8 k-steps of k16
    #pragma unroll
    for (int ks = 0; ks < 8; ks++) {
        uint32_t a[2][4];
        #pragma unroll
        for (int mt = 0; mt < 2; mt++)
            asm volatile("ldmatrix.sync.aligned.m8n8.x4.shared.b16 {%0,%1,%2,%3}, [%4];"
                : "=r"(a[mt][0]), "=r"(a[mt][1]), "=r"(a[mt][2]), "=r"(a[mt][3])
                : "r"(aAddr[mt] + ks * 32));
        uint32_t b[8][2];
        #pragma unroll
        for (int ntp = 0; ntp < 4; ntp++)
            asm volatile("ldmatrix.sync.aligned.m8n8.x4.shared.b16 {%0,%1,%2,%3}, [%4];"
                : "=r"(b[2*ntp][0]), "=r"(b[2*ntp][1]),
                  "=r"(b[2*ntp+1][0]), "=r"(b[2*ntp+1][1])
                : "r"(bAddr[ntp] + ks * 32));
        #pragma unroll
        for (int mt = 0; mt < 2; mt++)
            #pragma unroll
            for (int nt = 0; nt < 8; nt++)
                asm volatile(
                    "mma.sync.aligned.m16n8k16.row.col.f32.bf16.bf16.f32 "
                    "{%0,%1,%2,%3}, {%4,%5,%6,%7}, {%8,%9}, {%0,%1,%2,%3};"
                    : "+f"(acc[mt][nt][0]), "+f"(acc[mt][nt][1]),
                      "+f"(acc[mt][nt][2]), "+f"(acc[mt][nt][3])
                    : "r"(a[mt][0]), "r"(a[mt][1]), "r"(a[mt][2]), "r"(a[mt][3]),
                      "r"(b[nt][0]), "r"(b[nt][1]));
    }

    // ---- Epilogue: e = exp(sim/T) with self-diag masked; per-row partial sums
    int g = lane >> 2, t = lane & 3;
    bool diag = (blockIdx.x == blockIdx.y);

    #pragma unroll
    for (int mt = 0; mt < 2; mt++) {
        #pragma unroll
        for (int half = 0; half < 2; half++) {
            int i = rowBase + wm * 32 + mt * 16 + half * 8 + g;
            int jbase = colBase + wn * 64 + t * 2;
            float s = 0.0f;
            #pragma unroll
            for (int nt = 0; nt < 8; nt++) {
                #pragma unroll
                for (int e = 0; e < 2; e++) {
                    float v = acc[mt][nt][half * 2 + e];
                    float ex;
                    asm("ex2.approx.f32 %0, %1;" : "=f"(ex) : "f"(v * EXP_SCALE));
                    if (diag && (i == jbase + nt * 8 + e)) ex = 0.0f;
                    s += ex;
                }
            }
            s += __shfl_xor_sync(0xFFFFFFFFu, s, 1);
            s += __shfl_xor_sync(0xFFFFFFFFu, s, 2);
            if (t == 0) atomicAdd(&g_rowsum[i], s);
        }
    }
}

// ---------------------------------------------------------------------------
// Kernel 4: final scalar — mean_i( log(rowsum_i) - pos_i / T )
// ---------------------------------------------------------------------------
__global__ void reduce_kernel(float* __restrict__ out) {
    int tid = threadIdx.x;
    float acc = 0.0f;
    for (int i = tid; i < TWO_N; i += 256)
        acc += logf(g_rowsum[i]) - g_pos[i] * INV_T;
    #pragma unroll
    for (int o = 16; o > 0; o >>= 1) acc += __shfl_xor_sync(0xFFFFFFFFu, acc, o);
    __shared__ float sred[8];
    int lane = tid & 31, wid = tid >> 5;
    if (lane == 0) sred[wid] = acc;
    __syncthreads();
    if (tid == 0) {
        float tot = 0.0f;
        #pragma unroll
        for (int w = 0; w < 8; w++) tot += sred[w];
        out[0] = tot * (1.0f / (float)TWO_N);
    }
}

// ---------------------------------------------------------------------------
extern "C" void kernel_launch(void* const* d_in, const int* in_sizes, int n_in,
                              void* d_out, int out_size) {
    const float* z1 = (const float*)d_in[0];
    const float* z2 = (const float*)d_in[1];

    cudaFuncSetAttribute(simgemm_kernel,
                         cudaFuncAttributeMaxDynamicSharedMemorySize, SMEM_SZ);

    normalize_kernel<<<TWO_N, 128>>>(z1, z2);
    pos_kernel<<<TWO_N / 8, 256>>>();
    simgemm_kernel<<<dim3(TWO_N / BN, TWO_N / BM), 256, SMEM_SZ>>>();
    reduce_kernel<<<1, 256>>>((float*)d_out);
}

// round 3
// speedup vs baseline: 1.5468x; 1.5468x over previous
#include <cuda_runtime.h>
#include <cuda_bf16.h>
#include <cstdint>

// NT-Xent fused: N=4096, Z=128, T=0.5
#define TWO_N 8192
#define ZD 128
#define INV_T 2.0f
#define EXP_SCALE 2.8853900817779268f   // INV_T * log2(e)

#define BM 128
#define BN 128
#define ROW_TILES (TWO_N / BM)                    // 64
#define NUM_TILES (ROW_TILES * (ROW_TILES + 1) / 2)  // 2080 (upper triangle)
#define STRIDE 136                       // bf16 elems per smem row (128 + 8 pad)
#define SMEM_SZ (2 * BM * STRIDE * 2)    // 69632 bytes

// Scratch (device globals — no allocation allowed)
__device__ __nv_bfloat16 g_nrep_bf16[TWO_N * ZD];
__device__ float         g_nrep_f32 [TWO_N * ZD];
__device__ float         g_rowsum  [TWO_N];
__device__ float         g_pos     [TWO_N];
__device__ float         g_scalar;
__device__ unsigned int  g_ticket;

// ---------------------------------------------------------------------------
// Kernel 1: row-normalize reps = concat(z1, z2); emit f32 + bf16; zero accums
// ---------------------------------------------------------------------------
__global__ void normalize_kernel(const float* __restrict__ z1,
                                 const float* __restrict__ z2) {
    int row = blockIdx.x;
    int t = threadIdx.x;
    const float* src = (row < TWO_N / 2) ? (z1 + (size_t)row * ZD)
                                         : (z2 + (size_t)(row - TWO_N / 2) * ZD);
    float v = src[t];
    float s = v * v;
    #pragma unroll
    for (int o = 16; o > 0; o >>= 1) s += __shfl_xor_sync(0xFFFFFFFFu, s, o);
    __shared__ float ws[4];
    int lane = t & 31, wid = t >> 5;
    if (lane == 0) ws[wid] = s;
    __syncthreads();
    float tot = ws[0] + ws[1] + ws[2] + ws[3];
    float scale = 1.0f / fmaxf(sqrtf(tot), 1e-8f);
    float nv = v * scale;
    g_nrep_f32 [row * ZD + t] = nv;
    g_nrep_bf16[row * ZD + t] = __float2bfloat16(nv);
    if (t == 0) g_rowsum[row] = 0.0f;
    if (row == 0 && t == 0) { g_scalar = 0.0f; g_ticket = 0u; }
}

// ---------------------------------------------------------------------------
// Kernel 2: positives in fp32 — pos[i] = dot(nrep[i], nrep[(i+N) mod 2N])
// ---------------------------------------------------------------------------
__global__ void pos_kernel() {
    int wid = threadIdx.x >> 5, lane = threadIdx.x & 31;
    int row = blockIdx.x * 8 + wid;
    int peer = (row + TWO_N / 2) & (TWO_N - 1);
    const float* a = g_nrep_f32 + (size_t)row  * ZD;
    const float* b = g_nrep_f32 + (size_t)peer * ZD;
    float acc = 0.0f;
    #pragma unroll
    for (int k = lane; k < ZD; k += 32) acc = fmaf(a[k], b[k], acc);
    #pragma unroll
    for (int o = 16; o > 0; o >>= 1) acc += __shfl_xor_sync(0xFFFFFFFFu, acc, o);
    if (lane == 0) g_pos[row] = acc;
}

// ---------------------------------------------------------------------------
// Kernel 3: fused sim GEMM (mma.sync bf16) + exp + diag mask + row sums.
// Upper-triangular tile set only (sim is symmetric): off-diagonal tiles also
// accumulate their column sums into the transposed rows.
// CTA = 128x128 sim tile, 256 threads = 8 warps (4 m x 2 n), warp tile 32x64.
// ---------------------------------------------------------------------------
__global__ void __launch_bounds__(256, 2) simgemm_kernel() {
    extern __shared__ __nv_bfloat16 smem[];
    __nv_bfloat16* sA = smem;
    __nv_bfloat16* sB = smem + BM * STRIDE;

    int tid = threadIdx.x;
    int wid = tid >> 5, lane = tid & 31;

    // Decode linear tile index -> upper-triangle (ty <= tx)
    int rem = blockIdx.x, ty = 0;
    while (rem >= ROW_TILES - ty) { rem -= ROW_TILES - ty; ty++; }
    int tx = ty + rem;

    int rowBase = ty * BM;
    int colBase = tx * BN;
    bool diag = (tx == ty);

    // ---- Load A/B tiles [128 x 128] bf16 into padded smem (uint4 = 8 bf16)
    #pragma unroll
    for (int it = 0; it < 8; it++) {
        int idx = it * 256 + tid;          // 2048 16B-chunks per tile
        int r = idx >> 4, c = idx & 15;
        uint4 va = *(const uint4*)(g_nrep_bf16 + (size_t)(rowBase + r) * ZD + c * 8);
        *(uint4*)(sA + r * STRIDE + c * 8) = va;
        uint4 vb = *(const uint4*)(g_nrep_bf16 + (size_t)(colBase + r) * ZD + c * 8);
        *(uint4*)(sB + r * STRIDE + c * 8) = vb;
    }
    __syncthreads();

    int wm = wid & 3;        // warp row (4)
    int wn = wid >> 2;       // warp col (2)

    float acc[2][8][4];
    #pragma unroll
    for (int mt = 0; mt < 2; mt++)
        #pragma unroll
        for (int nt = 0; nt < 8; nt++)
            #pragma unroll
            for (int e = 0; e < 4; e++) acc[mt][nt][e] = 0.0f;

    // ldmatrix base addresses (per lane); k advances by 32B per k-step
    uint32_t aAddr[2];
    #pragma unroll
    for (int mt = 0; mt < 2; mt++) {
        int row = wm * 32 + mt * 16 + (lane & 15);
        int k = (lane >> 4) * 8;
        aAddr[mt] = (uint32_t)__cvta_generic_to_shared(sA + row * STRIDE + k);
    }
    uint32_t bAddr[4];
    #pragma unroll
    for (int ntp = 0; ntp < 4; ntp++) {
        int n = wn * 64 + ntp * 16 + ((lane >> 4) & 1) * 8 + (lane & 7);
        int k = ((lane >> 3) & 1) * 8;
        bAddr[ntp] = (uint32_t)__cvta_generic_to_shared(sB + n * STRIDE + k);
    }

    // ---- Mainloop: 8 k-steps of k16
    #pragma unroll
    for (int ks = 0; ks < 8; ks++) {
        uint32_t a[2][4];
        #pragma unroll
        for (int mt = 0; mt < 2; mt++)
            asm volatile("ldmatrix.sync.aligned.m8n8.x4.shared.b16 {%0,%1,%2,%3}, [%4];"
                : "=r"(a[mt][0]), "=r"(a[mt][1]), "=r"(a[mt][2]), "=r"(a[mt][3])
                : "r"(aAddr[mt] + ks * 32));
        uint32_t b[8][2];
        #pragma unroll
        for (int ntp = 0; ntp < 4; ntp++)
            asm volatile("ldmatrix.sync.aligned.m8n8.x4.shared.b16 {%0,%1,%2,%3}, [%4];"
                : "=r"(b[2*ntp][0]), "=r"(b[2*ntp][1]),
                  "=r"(b[2*ntp+1][0]), "=r"(b[2*ntp+1][1])
                : "r"(bAddr[ntp] + ks * 32));
        #pragma unroll
        for (int mt = 0; mt < 2; mt++)
            #pragma unroll
            for (int nt = 0; nt < 8; nt++)
                asm volatile(
                    "mma.sync.aligned.m16n8k16.row.col.f32.bf16.bf16.f32 "
                    "{%0,%1,%2,%3}, {%4,%5,%6,%7}, {%8,%9}, {%0,%1,%2,%3};"
                    : "+f"(acc[mt][nt][0]), "+f"(acc[mt][nt][1]),
                      "+f"(acc[mt][nt][2]), "+f"(acc[mt][nt][3])
                    : "r"(a[mt][0]), "r"(a[mt][1]), "r"(a[mt][2]), "r"(a[mt][3]),
                      "r"(b[nt][0]), "r"(b[nt][1]));
    }

    // ---- Epilogue: e = exp(sim/T), self-diag masked.
    // Row sums -> rows in [rowBase, rowBase+128).
    // Off-diag tiles: also column sums -> rows in [colBase, colBase+128).
    int g = lane >> 2, t = lane & 3;

    float colacc[16];
    #pragma unroll
    for (int c = 0; c < 16; c++) colacc[c] = 0.0f;

    #pragma unroll
    for (int mt = 0; mt < 2; mt++) {
        #pragma unroll
        for (int half = 0; half < 2; half++) {
            int i = rowBase + wm * 32 + mt * 16 + half * 8 + g;
            int jbase = colBase + wn * 64 + t * 2;
            float s = 0.0f;
            #pragma unroll
            for (int nt = 0; nt < 8; nt++) {
                #pragma unroll
                for (int e = 0; e < 2; e++) {
                    float v = acc[mt][nt][half * 2 + e];
                    float ex;
                    asm("ex2.approx.f32 %0, %1;" : "=f"(ex) : "f"(v * EXP_SCALE));
                    if (diag && (i == jbase + nt * 8 + e)) ex = 0.0f;
                    s += ex;
                    colacc[nt * 2 + e] += ex;
                }
            }
            s += __shfl_xor_sync(0xFFFFFFFFu, s, 1);
            s += __shfl_xor_sync(0xFFFFFFFFu, s, 2);
            if (t == 0) atomicAdd(&g_rowsum[i], s);
        }
    }

    if (!diag) {
        // Reduce column partials across the 8 row-groups (lanes xor 4,8,16
        // preserve t), then lanes with g==0 own 16 columns each.
        #pragma unroll
        for (int c = 0; c < 16; c++) {
            float v = colacc[c];
            v += __shfl_xor_sync(0xFFFFFFFFu, v, 4);
            v += __shfl_xor_sync(0xFFFFFFFFu, v, 8);
            v += __shfl_xor_sync(0xFFFFFFFFu, v, 16);
            colacc[c] = v;
        }
        if (g == 0) {
            int jbase = colBase + wn * 64 + t * 2;
            #pragma unroll
            for (int c = 0; c < 16; c++) {
                int j = jbase + (c >> 1) * 8 + (c & 1);
                atomicAdd(&g_rowsum[j], colacc[c]);
            }
        }
    }
}

// ---------------------------------------------------------------------------
// Kernel 4: mean_i( log(rowsum_i) - pos_i / T ), 32 blocks + ticket finish
// ---------------------------------------------------------------------------
__global__ void reduce_kernel(float* __restrict__ out) {
    int tid = threadIdx.x;
    int gid = blockIdx.x * 256 + tid;
    float acc = logf(g_rowsum[gid]) - g_pos[gid] * INV_T;
    #pragma unroll
    for (int o = 16; o > 0; o >>= 1) acc += __shfl_xor_sync(0xFFFFFFFFu, acc, o);
    __shared__ float sred[8];
    int lane = tid & 31, wid = tid >> 5;
    if (lane == 0) sred[wid] = acc;
    __syncthreads();
    if (tid == 0) {
        float tot = 0.0f;
        #pragma unroll
        for (int w = 0; w < 8; w++) tot += sred[w];
        atomicAdd(&g_scalar, tot);
        __threadfence();
        unsigned int ticket = atomicInc(&g_ticket, 0xFFFFFFFFu);
        if (ticket == gridDim.x - 1) {
            float total = atomicAdd(&g_scalar, 0.0f);
            out[0] = total * (1.0f / (float)TWO_N);
        }
    }
}

// ---------------------------------------------------------------------------
extern "C" void kernel_launch(void* const* d_in, const int* in_sizes, int n_in,
                              void* d_out, int out_size) {
    const float* z1 = (const float*)d_in[0];
    const float* z2 = (const float*)d_in[1];

    cudaFuncSetAttribute(simgemm_kernel,
                         cudaFuncAttributeMaxDynamicSharedMemorySize, SMEM_SZ);

    normalize_kernel<<<TWO_N, 128>>>(z1, z2);
    pos_kernel<<<TWO_N / 8, 256>>>();
    simgemm_kernel<<<NUM_TILES, 256, SMEM_SZ>>>();
    reduce_kernel<<<TWO_N / 256, 256>>>((float*)d_out);
}